// round 16
// baseline (speedup 1.0000x reference)
#include <cuda_runtime.h>
#include <cuda_bf16.h>
#include <math.h>
#include <stdint.h>

// Problem constants
#define B_   4096
#define E_   16384
#define DIM_ 4096
#define NTHREADS 256

// GEMM tiling: 128x128 CTA tile, 8 warps (4m x 2n), 2 CTAs/SM  (LOCKED: round-14 champion)
#define TILE_M 128
#define TILE_N 128
#define KCHUNK 64                // bf16 elems per K chunk = 128 bytes per row
#define NCHUNKS (DIM_ / KCHUNK)  // 64
#define NSTAGES 3

#define NGROUPS (E_ / 32)        // 512 groups of 32 cols per row
#define MARGIN_ULPS 3u           // bf16-validated margin (rounds 6-8, 14)
#define MAXCAND 1024             // = total keys per row -> overflow impossible

// dynamic smem layout (GEMM)
#define SOFF_EN   0              // 128 floats enorm
#define SOFF_XN   512            // 128 floats xnorm
#define SOFF_STAGE 1024
#define STAGE_BYTES 32768        // Xb 16K | Wb 16K
#define SMEM_TOTAL (SOFF_STAGE + NSTAGES * STAGE_BYTES)  // 99328 -> 2 CTAs/SM

// ---------------- device scratch ----------------
__device__ unsigned short     g_Xb[B_ * DIM_];
__device__ unsigned short     g_Wb[E_ * DIM_];
__device__ unsigned long long g_top2[(size_t)B_ * NGROUPS * 2];   // 32MB
__device__ float              g_xnorm[B_];
__device__ float              g_enorm[E_];
__device__ unsigned long long g_best[B_];
__device__ int                g_counts[E_];
__device__ double             g_loss_partial[B_];

// ---------------- helpers ----------------
__device__ __forceinline__ uint32_t smem_to_u32(const void* p) {
    uint32_t a;
    asm("{ .reg .u64 t; cvta.to.shared.u64 t, %1; cvt.u32.u64 %0, t; }" : "=r"(a) : "l"(p));
    return a;
}

__device__ __forceinline__ void ldsm4(uint32_t* r, uint32_t addr) {
    asm volatile("ldmatrix.sync.aligned.m8n8.x4.shared.b16 {%0,%1,%2,%3}, [%4];"
        : "=r"(r[0]), "=r"(r[1]), "=r"(r[2]), "=r"(r[3]) : "r"(addr));
}

__device__ __forceinline__ void mma_bf16(float* d, const uint32_t* a, const uint32_t* b) {
    asm volatile(
        "mma.sync.aligned.m16n8k16.row.col.f32.bf16.bf16.f32 "
        "{%0,%1,%2,%3}, {%4,%5,%6,%7}, {%8,%9}, {%0,%1,%2,%3};"
        : "+f"(d[0]), "+f"(d[1]), "+f"(d[2]), "+f"(d[3])
        : "r"(a[0]), "r"(a[1]), "r"(a[2]), "r"(a[3]), "r"(b[0]), "r"(b[1]));
}

__device__ __forceinline__ unsigned int f2ord(float f) {
    unsigned int u = __float_as_uint(f);
    return (u & 0x80000000u) ? ~u : (u | 0x80000000u);
}

__device__ double block_reduce256(double v) {
    __shared__ double sm[NTHREADS];
    int t = threadIdx.x;
    __syncthreads();
    sm[t] = v;
    __syncthreads();
    #pragma unroll
    for (int s = NTHREADS / 2; s > 0; s >>= 1) {
        if (t < s) sm[t] += sm[t + s];
        __syncthreads();
    }
    return sm[0];
}

// ---------------- init ----------------
__global__ void vq_init() {
    int t = blockIdx.x * blockDim.x + threadIdx.x;
    if (t < E_) g_counts[t] = 0;
}

// ---------------- fused row norm + bf16 convert ----------------
__global__ void vq_prep(const float* __restrict__ src,
                        unsigned short* __restrict__ dst,
                        float* __restrict__ norm) {
    int r = blockIdx.x;
    const float4* p = (const float4*)(src + (size_t)r * DIM_);
    uint2* o = (uint2*)(dst + (size_t)r * DIM_);
    double s = 0.0;
    #pragma unroll
    for (int i = 0; i < DIM_ / 4 / NTHREADS; ++i) {
        int c = threadIdx.x + i * NTHREADS;
        float4 v = p[c];
        s += (double)v.x * v.x + (double)v.y * v.y
           + (double)v.z * v.z + (double)v.w * v.w;
        uint2 q;
        q.x = (uint32_t)__bfloat16_as_ushort(__float2bfloat16(v.x))
            | ((uint32_t)__bfloat16_as_ushort(__float2bfloat16(v.y)) << 16);
        q.y = (uint32_t)__bfloat16_as_ushort(__float2bfloat16(v.z))
            | ((uint32_t)__bfloat16_as_ushort(__float2bfloat16(v.w)) << 16);
        o[c] = q;
    }
    double tot = block_reduce256(s);
    if (threadIdx.x == 0) norm[r] = (float)tot;
}

// ---------------- coarse bf16 HMMA GEMM (128x128 tile, 8 warps, 2 CTAs/SM) + top-2 ----------------
__global__ void __launch_bounds__(NTHREADS, 2)
vq_gemm_mma(const unsigned short* __restrict__ Xb, const unsigned short* __restrict__ Wb) {
    extern __shared__ char smem[];
    uint32_t sbase = smem_to_u32(smem);
    float* sEn = (float*)(smem + SOFF_EN);
    float* sXn = (float*)(smem + SOFF_XN);

    const int tid  = threadIdx.x;
    const int lane = tid & 31;
    const int wid  = tid >> 5;           // 0..7
    const int m0 = blockIdx.x * TILE_M;
    const int n0 = blockIdx.y * TILE_N;
    const int wm = (wid >> 1) * 32;      // warp m offset: 0/32/64/96
    const int wn = (wid & 1) * 64;       // warp n offset: 0/64

    if (tid < 128) {
        sEn[tid] = g_enorm[n0 + tid];
        sXn[tid] = g_xnorm[m0 + tid];
    }

    // cp.async one K chunk (Xb 128 rows, Wb 128 rows) into stage c%3
    auto load_chunk = [&](int c) {
        int st = c % NSTAGES;
        int k0 = c * KCHUNK;
        uint32_t stage = sbase + SOFF_STAGE + st * STAGE_BYTES;
        #pragma unroll
        for (int i = 0; i < 8; ++i) {
            int id = i * NTHREADS + tid;       // 0..2047
            int q   = id & 1023;
            int row = q >> 3;                  // 0..127
            int c16 = q & 7;
            uint32_t off = (uint32_t)(row * 128 + c16 * 16);
            off ^= ((off >> 3) & 0x70);        // SW128 swizzle
            const unsigned short* g;
            uint32_t sd;
            if (id < 1024) { g = Xb + (size_t)(m0 + row) * DIM_ + k0 + c16 * 8; sd = stage + off; }
            else           { g = Wb + (size_t)(n0 + row) * DIM_ + k0 + c16 * 8; sd = stage + 16384 + off; }
            asm volatile("cp.async.cg.shared.global [%0], [%1], 16;" :: "r"(sd), "l"(g) : "memory");
        }
        asm volatile("cp.async.commit_group;" ::: "memory");
    };

    load_chunk(0);
    load_chunk(1);

    float acc[2][8][4];
    #pragma unroll
    for (int i = 0; i < 2; ++i)
        #pragma unroll
        for (int j = 0; j < 8; ++j)
            #pragma unroll
            for (int r = 0; r < 4; ++r) acc[i][j][r] = 0.0f;

    const int aRow  = lane & 15;
    const int aKoff = (lane >> 4) * 16;
    const int bRow  = ((lane >> 4) << 3) + (lane & 7);
    const int bKoff = ((lane >> 3) & 1) * 16;

    for (int c = 0; c < NCHUNKS; ++c) {
        asm volatile("cp.async.wait_group 1;" ::: "memory");
        __syncthreads();

        // prefetch c+2 into stage (c+2)%3 == stage(c-1): consumed last iteration,
        // and this iteration's __syncthreads fences all readers. (round-8-safe)
        if (c + 2 < NCHUNKS) load_chunk(c + 2);
        else asm volatile("cp.async.commit_group;" ::: "memory");

        int st = c % NSTAGES;
        uint32_t stg = sbase + SOFF_STAGE + st * STAGE_BYTES;

        #pragma unroll
        for (int s = 0; s < 4; ++s) {
            uint32_t af[2][4], bf[8][2];
            #pragma unroll
            for (int mi = 0; mi < 2; ++mi) {
                uint32_t off = (uint32_t)((wm + mi * 16 + aRow) * 128 + s * 32 + aKoff);
                off ^= ((off >> 3) & 0x70);
                ldsm4(af[mi], stg + off);
            }
            #pragma unroll
            for (int ni2 = 0; ni2 < 4; ++ni2) {
                uint32_t off = (uint32_t)((wn + ni2 * 16 + bRow) * 128 + s * 32 + bKoff);
                off ^= ((off >> 3) & 0x70);
                uint32_t t[4];
                ldsm4(t, stg + 16384 + off);
                bf[2 * ni2][0] = t[0]; bf[2 * ni2][1] = t[1];
                bf[2 * ni2 + 1][0] = t[2]; bf[2 * ni2 + 1][1] = t[3];
            }
            #pragma unroll
            for (int mi = 0; mi < 2; ++mi)
                #pragma unroll
                for (int ni = 0; ni < 8; ++ni)
                    mma_bf16(acc[mi][ni], af[mi], bf[ni]);
        }
    }
    __syncthreads();

    // epilogue: per-row top-2 within each of this warp's two 32-col groups
    const int gr = lane >> 2;           // row in 8-group
    const int gc = lane & 3;
    const int gc2 = gc * 2;
    const int group0 = (n0 + wn) >> 5;  // first global 32-col group id

    #pragma unroll
    for (int mi = 0; mi < 2; ++mi) {
        #pragma unroll
        for (int half = 0; half < 2; ++half) {
            int rl = wm + mi * 16 + gr + half * 8;
            float xn = sXn[rl];
            #pragma unroll
            for (int grp = 0; grp < 2; ++grp) {
                unsigned long long k1 = ~0ull, k2 = ~0ull;
                #pragma unroll
                for (int ni = grp * 4; ni < grp * 4 + 4; ++ni)
                    #pragma unroll
                    for (int j = 0; j < 2; ++j) {
                        int nloc = wn + ni * 8 + gc2 + j;
                        float d = __fadd_rn(__fadd_rn(xn, sEn[nloc]),
                                            __fmul_rn(-2.0f, acc[mi][ni][half * 2 + j]));
                        unsigned long long key =
                            ((unsigned long long)f2ord(d) << 32) | (unsigned)(n0 + nloc);
                        if (key < k1) { k2 = k1; k1 = key; }
                        else if (key < k2) { k2 = key; }
                    }
                // merge top-2 across the 4 lanes holding this row
                #pragma unroll
                for (int x = 1; x <= 2; x <<= 1) {
                    unsigned long long o1 = __shfl_xor_sync(0xffffffffu, k1, x);
                    unsigned long long o2 = __shfl_xor_sync(0xffffffffu, k2, x);
                    unsigned long long n1 = (k1 < o1) ? k1 : o1;
                    unsigned long long mx = (k1 < o1) ? o1 : k1;
                    unsigned long long mn2 = (k2 < o2) ? k2 : o2;
                    k1 = n1;
                    k2 = (mx < mn2) ? mx : mn2;
                }
                if (gc == 0) {
                    size_t base = ((size_t)(m0 + rl) * NGROUPS + group0 + grp) * 2;
                    g_top2[base]     = k1;
                    g_top2[base + 1] = k2;
                }
            }
        }
    }
}

// ---------------- candidates + exact rescore + fused quant/loss/histogram ----------------
__global__ void __launch_bounds__(NTHREADS)
vq_candidates(const float* __restrict__ X, const float* __restrict__ W,
              float* __restrict__ qout) {
    __shared__ unsigned long long skey[NTHREADS];
    __shared__ int scand[MAXCAND];
    __shared__ int scnt;
    __shared__ unsigned long long sthr;
    __shared__ unsigned long long sbest;

    int b = blockIdx.x;
    int t = threadIdx.x;
    int lane = t & 31;
    int wid  = t >> 5;
    const unsigned long long* keys = g_top2 + (size_t)b * NGROUPS * 2;

    // per-thread min over 4 keys, then tree-min
    unsigned long long mk = ~0ull;
    unsigned long long my[4];
    #pragma unroll
    for (int i = 0; i < 4; ++i) {
        my[i] = keys[t + i * NTHREADS];
        if (my[i] < mk) mk = my[i];
    }
    skey[t] = mk;
    __syncthreads();
    #pragma unroll
    for (int s = NTHREADS / 2; s > 0; s >>= 1) {
        if (t < s && skey[t + s] < skey[t]) skey[t] = skey[t + s];
        __syncthreads();
    }
    if (t == 0) {
        scnt = 0;
        sbest = ~0ull;
        unsigned int mord = (unsigned int)(skey[0] >> 32);
        sthr = ((unsigned long long)(mord + MARGIN_ULPS) << 32) | 0xffffffffull;
    }
    __syncthreads();

    unsigned long long thr = sthr;
    #pragma unroll
    for (int i = 0; i < 4; ++i) {
        if (my[i] <= thr) {
            int pos = atomicAdd(&scnt, 1);
            scand[pos] = (int)(my[i] & 0xffffffffu);   // MAXCAND = key count: no drop possible
        }
    }
    __syncthreads();
    int n = scnt;

    // exact rescore: one candidate per warp, double warp-shuffle reduction
    const float* xr = X + (size_t)b * DIM_;
    float xn = g_xnorm[b];
    for (int i = wid; i < n; i += NTHREADS / 32) {
        int col = scand[i];
        const float* wr = W + (size_t)col * DIM_;
        double s = 0.0;
        for (int k = lane; k < DIM_; k += 32)
            s += (double)xr[k] * (double)wr[k];
        #pragma unroll
        for (int off = 16; off > 0; off >>= 1)
            s += __shfl_down_sync(0xffffffffu, s, off);
        if (lane == 0) {
            float d = __fadd_rn(__fadd_rn(xn, g_enorm[col]), -2.0f * (float)s);
            unsigned long long key = ((unsigned long long)f2ord(d) << 32) | (unsigned)col;
            atomicMin(&sbest, key);
        }
    }
    __syncthreads();
    int idx = (int)(sbest & 0xffffffffu);
    if (t == 0) {
        g_best[b] = sbest;
        atomicAdd(&g_counts[idx], 1);                  // fused histogram
    }

    // fused quant (STE) + loss partial: X row and W[idx] row are L2-hot from rescore
    const float4* xr4 = (const float4*)xr;
    const float4* qr4 = (const float4*)(W + (size_t)idx * DIM_);
    float* o = qout + (size_t)b * DIM_;   // 4B-aligned only: scalar stores
    double ls = 0.0;
    for (int c = t; c < DIM_ / 4; c += NTHREADS) {
        float4 x = xr4[c];
        float4 q = qr4[c];
        float d0 = __fadd_rn(q.x, -x.x);
        float d1 = __fadd_rn(q.y, -x.y);
        float d2 = __fadd_rn(q.z, -x.z);
        float d3 = __fadd_rn(q.w, -x.w);
        o[4 * c + 0] = __fadd_rn(x.x, d0);
        o[4 * c + 1] = __fadd_rn(x.y, d1);
        o[4 * c + 2] = __fadd_rn(x.z, d2);
        o[4 * c + 3] = __fadd_rn(x.w, d3);
        ls += (double)d0 * d0 + (double)d1 * d1 + (double)d2 * d2 + (double)d3 * d3;
    }
    double tot = block_reduce256(ls);
    if (t == 0) g_loss_partial[b] = tot;
}

// ---------------- one-hot encodings (float2 stores: base is 8B-aligned only) ----------------
__global__ void vq_encodings(float* __restrict__ enc) {
    long long gid = (long long)blockIdx.x * blockDim.x + threadIdx.x;
    const long long total = (long long)B_ * (E_ / 2);
    if (gid >= total) return;
    int b  = (int)(gid >> 13);      // E_/2 = 8192 float2 per row
    int c2 = (int)(gid & 8191);
    int idx = (int)(g_best[b] & 0xffffffffu);
    int c = c2 * 2;
    float2 v;
    v.x = (c == idx) ? 1.0f : 0.0f;
    v.y = (c + 1 == idx) ? 1.0f : 0.0f;
    ((float2*)enc)[gid] = v;
}

// ---------------- finalize ----------------
__global__ void vq_finalize(float* __restrict__ out_loss, float* __restrict__ out_perp) {
    int t = threadIdx.x;
    double s = 0.0;
    for (int i = t; i < B_; i += NTHREADS) s += g_loss_partial[i];
    double tot = block_reduce256(s);

    double h = 0.0;
    for (int e = t; e < E_; e += NTHREADS) {
        float p = (float)g_counts[e] * (1.0f / (float)B_);
        float term = p * logf(p + 1e-10f);
        h -= (double)term;
    }
    double H = block_reduce256(h);

    if (t == 0) {
        double m = tot / ((double)B_ * (double)DIM_);
        float mf = (float)m;
        out_loss[0] = __fadd_rn(mf, 0.25f * mf);
        out_perp[0] = expf((float)H);
    }
}

// ---------------- launch ----------------
extern "C" void kernel_launch(void* const* d_in, const int* in_sizes, int n_in,
                              void* d_out, int out_size) {
    const float* X;
    const float* W;
    if (in_sizes[0] == B_ * DIM_) {
        X = (const float*)d_in[0];
        W = (const float*)d_in[1];
    } else {
        X = (const float*)d_in[1];
        W = (const float*)d_in[0];
    }

    float* out = (float*)d_out;
    float* out_loss = out;
    float* out_q    = out + 1;
    float* out_perp = out + 1 + (size_t)B_ * DIM_;
    float* out_enc  = out + 2 + (size_t)B_ * DIM_;

    float* xnorm;  cudaGetSymbolAddress((void**)&xnorm, g_xnorm);
    float* enorm;  cudaGetSymbolAddress((void**)&enorm, g_enorm);
    unsigned short *xb, *wb;
    cudaGetSymbolAddress((void**)&xb, g_Xb);
    cudaGetSymbolAddress((void**)&wb, g_Wb);

    vq_init<<<E_ / NTHREADS, NTHREADS>>>();
    vq_prep<<<B_, NTHREADS>>>(X, xb, xnorm);
    vq_prep<<<E_, NTHREADS>>>(W, wb, enorm);

    cudaFuncSetAttribute(vq_gemm_mma, cudaFuncAttributeMaxDynamicSharedMemorySize, SMEM_TOTAL);
    dim3 grid(B_ / TILE_M, E_ / TILE_N);   // x = M fastest: B tiles reused in L2
    vq_gemm_mma<<<grid, NTHREADS, SMEM_TOTAL>>>(xb, wb);

    vq_candidates<<<B_, NTHREADS>>>(X, W, out_q);

    long long enc_threads = (long long)B_ * (E_ / 2);
    vq_encodings<<<(unsigned)((enc_threads + NTHREADS - 1) / NTHREADS), NTHREADS>>>(out_enc);

    vq_finalize<<<1, NTHREADS>>>(out_loss, out_perp);
}

// round 17
// speedup vs baseline: 1.0422x; 1.0422x over previous
#include <cuda_runtime.h>
#include <cuda_bf16.h>
#include <math.h>
#include <stdint.h>

// Problem constants
#define B_   4096
#define E_   16384
#define DIM_ 4096
#define NTHREADS 256

// GEMM tiling: 128x128 CTA tile, 8 warps (4m x 2n), 2 CTAs/SM  (LOCKED: round-14 champion)
#define TILE_M 128
#define TILE_N 128
#define KCHUNK 64                // bf16 elems per K chunk = 128 bytes per row
#define NCHUNKS (DIM_ / KCHUNK)  // 64
#define NSTAGES 3

#define NGROUPS (E_ / 32)        // 512 groups of 32 cols per row
#define MARGIN_ULPS 3u           // bf16-validated margin (rounds 6-8, 14)
#define MAXCAND 1024             // = total keys per row -> overflow impossible

// dynamic smem layout (GEMM)
#define SOFF_EN   0              // 128 floats enorm
#define SOFF_XN   512            // 128 floats xnorm
#define SOFF_STAGE 1024
#define STAGE_BYTES 32768        // Xb 16K | Wb 16K
#define SMEM_TOTAL (SOFF_STAGE + NSTAGES * STAGE_BYTES)  // 99328 -> 2 CTAs/SM

// ---------------- device scratch ----------------
__device__ unsigned short     g_Xb[B_ * DIM_];
__device__ unsigned short     g_Wb[E_ * DIM_];
__device__ unsigned long long g_top2[(size_t)B_ * NGROUPS * 2];   // 32MB
__device__ float              g_xnorm[B_];
__device__ float              g_enorm[E_];
__device__ unsigned long long g_best[B_];
__device__ int                g_counts[E_];
__device__ double             g_loss_partial[B_];

// ---------------- helpers ----------------
__device__ __forceinline__ uint32_t smem_to_u32(const void* p) {
    uint32_t a;
    asm("{ .reg .u64 t; cvta.to.shared.u64 t, %1; cvt.u32.u64 %0, t; }" : "=r"(a) : "l"(p));
    return a;
}

__device__ __forceinline__ void ldsm4(uint32_t* r, uint32_t addr) {
    asm volatile("ldmatrix.sync.aligned.m8n8.x4.shared.b16 {%0,%1,%2,%3}, [%4];"
        : "=r"(r[0]), "=r"(r[1]), "=r"(r[2]), "=r"(r[3]) : "r"(addr));
}

__device__ __forceinline__ void mma_bf16(float* d, const uint32_t* a, const uint32_t* b) {
    asm volatile(
        "mma.sync.aligned.m16n8k16.row.col.f32.bf16.bf16.f32 "
        "{%0,%1,%2,%3}, {%4,%5,%6,%7}, {%8,%9}, {%0,%1,%2,%3};"
        : "+f"(d[0]), "+f"(d[1]), "+f"(d[2]), "+f"(d[3])
        : "r"(a[0]), "r"(a[1]), "r"(a[2]), "r"(a[3]), "r"(b[0]), "r"(b[1]));
}

__device__ __forceinline__ unsigned int f2ord(float f) {
    unsigned int u = __float_as_uint(f);
    return (u & 0x80000000u) ? ~u : (u | 0x80000000u);
}

__device__ double block_reduce256(double v) {
    __shared__ double sm[NTHREADS];
    int t = threadIdx.x;
    __syncthreads();
    sm[t] = v;
    __syncthreads();
    #pragma unroll
    for (int s = NTHREADS / 2; s > 0; s >>= 1) {
        if (t < s) sm[t] += sm[t + s];
        __syncthreads();
    }
    return sm[0];
}

// ---------------- init ----------------
__global__ void vq_init() {
    int t = blockIdx.x * blockDim.x + threadIdx.x;
    if (t < E_) g_counts[t] = 0;
}

// ---------------- fused row norm + bf16 convert ----------------
__global__ void vq_prep(const float* __restrict__ src,
                        unsigned short* __restrict__ dst,
                        float* __restrict__ norm) {
    int r = blockIdx.x;
    const float4* p = (const float4*)(src + (size_t)r * DIM_);
    uint2* o = (uint2*)(dst + (size_t)r * DIM_);
    double s = 0.0;
    #pragma unroll
    for (int i = 0; i < DIM_ / 4 / NTHREADS; ++i) {
        int c = threadIdx.x + i * NTHREADS;
        float4 v = p[c];
        s += (double)v.x * v.x + (double)v.y * v.y
           + (double)v.z * v.z + (double)v.w * v.w;
        uint2 q;
        q.x = (uint32_t)__bfloat16_as_ushort(__float2bfloat16(v.x))
            | ((uint32_t)__bfloat16_as_ushort(__float2bfloat16(v.y)) << 16);
        q.y = (uint32_t)__bfloat16_as_ushort(__float2bfloat16(v.z))
            | ((uint32_t)__bfloat16_as_ushort(__float2bfloat16(v.w)) << 16);
        o[c] = q;
    }
    double tot = block_reduce256(s);
    if (threadIdx.x == 0) norm[r] = (float)tot;
}

// ---------------- coarse bf16 HMMA GEMM (128x128 tile, 8 warps, 2 CTAs/SM) + top-2 ----------------
__global__ void __launch_bounds__(NTHREADS, 2)
vq_gemm_mma(const unsigned short* __restrict__ Xb, const unsigned short* __restrict__ Wb) {
    extern __shared__ char smem[];
    uint32_t sbase = smem_to_u32(smem);
    float* sEn = (float*)(smem + SOFF_EN);
    float* sXn = (float*)(smem + SOFF_XN);

    const int tid  = threadIdx.x;
    const int lane = tid & 31;
    const int wid  = tid >> 5;           // 0..7
    const int m0 = blockIdx.x * TILE_M;
    const int n0 = blockIdx.y * TILE_N;
    const int wm = (wid >> 1) * 32;      // warp m offset: 0/32/64/96
    const int wn = (wid & 1) * 64;       // warp n offset: 0/64

    if (tid < 128) {
        sEn[tid] = g_enorm[n0 + tid];
        sXn[tid] = g_xnorm[m0 + tid];
    }

    // cp.async one K chunk (Xb 128 rows, Wb 128 rows) into stage c%3
    auto load_chunk = [&](int c) {
        int st = c % NSTAGES;
        int k0 = c * KCHUNK;
        uint32_t stage = sbase + SOFF_STAGE + st * STAGE_BYTES;
        #pragma unroll
        for (int i = 0; i < 8; ++i) {
            int id = i * NTHREADS + tid;       // 0..2047
            int q   = id & 1023;
            int row = q >> 3;                  // 0..127
            int c16 = q & 7;
            uint32_t off = (uint32_t)(row * 128 + c16 * 16);
            off ^= ((off >> 3) & 0x70);        // SW128 swizzle
            const unsigned short* g;
            uint32_t sd;
            if (id < 1024) { g = Xb + (size_t)(m0 + row) * DIM_ + k0 + c16 * 8; sd = stage + off; }
            else           { g = Wb + (size_t)(n0 + row) * DIM_ + k0 + c16 * 8; sd = stage + 16384 + off; }
            asm volatile("cp.async.cg.shared.global [%0], [%1], 16;" :: "r"(sd), "l"(g) : "memory");
        }
        asm volatile("cp.async.commit_group;" ::: "memory");
    };

    load_chunk(0);
    load_chunk(1);

    float acc[2][8][4];
    #pragma unroll
    for (int i = 0; i < 2; ++i)
        #pragma unroll
        for (int j = 0; j < 8; ++j)
            #pragma unroll
            for (int r = 0; r < 4; ++r) acc[i][j][r] = 0.0f;

    const int aRow  = lane & 15;
    const int aKoff = (lane >> 4) * 16;
    const int bRow  = ((lane >> 4) << 3) + (lane & 7);
    const int bKoff = ((lane >> 3) & 1) * 16;

    for (int c = 0; c < NCHUNKS; ++c) {
        asm volatile("cp.async.wait_group 1;" ::: "memory");
        __syncthreads();

        // prefetch c+2 into stage (c+2)%3 == stage(c-1): consumed last iteration,
        // and this iteration's __syncthreads fences all readers. (round-8-safe)
        if (c + 2 < NCHUNKS) load_chunk(c + 2);
        else asm volatile("cp.async.commit_group;" ::: "memory");

        int st = c % NSTAGES;
        uint32_t stg = sbase + SOFF_STAGE + st * STAGE_BYTES;

        #pragma unroll
        for (int s = 0; s < 4; ++s) {
            uint32_t af[2][4], bf[8][2];
            #pragma unroll
            for (int mi = 0; mi < 2; ++mi) {
                uint32_t off = (uint32_t)((wm + mi * 16 + aRow) * 128 + s * 32 + aKoff);
                off ^= ((off >> 3) & 0x70);
                ldsm4(af[mi], stg + off);
            }
            #pragma unroll
            for (int ni2 = 0; ni2 < 4; ++ni2) {
                uint32_t off = (uint32_t)((wn + ni2 * 16 + bRow) * 128 + s * 32 + bKoff);
                off ^= ((off >> 3) & 0x70);
                uint32_t t[4];
                ldsm4(t, stg + 16384 + off);
                bf[2 * ni2][0] = t[0]; bf[2 * ni2][1] = t[1];
                bf[2 * ni2 + 1][0] = t[2]; bf[2 * ni2 + 1][1] = t[3];
            }
            #pragma unroll
            for (int mi = 0; mi < 2; ++mi)
                #pragma unroll
                for (int ni = 0; ni < 8; ++ni)
                    mma_bf16(acc[mi][ni], af[mi], bf[ni]);
        }
    }
    __syncthreads();

    // epilogue: per-row top-2 within each of this warp's two 32-col groups
    const int gr = lane >> 2;           // row in 8-group
    const int gc = lane & 3;
    const int gc2 = gc * 2;
    const int group0 = (n0 + wn) >> 5;  // first global 32-col group id

    #pragma unroll
    for (int mi = 0; mi < 2; ++mi) {
        #pragma unroll
        for (int half = 0; half < 2; ++half) {
            int rl = wm + mi * 16 + gr + half * 8;
            float xn = sXn[rl];
            #pragma unroll
            for (int grp = 0; grp < 2; ++grp) {
                unsigned long long k1 = ~0ull, k2 = ~0ull;
                #pragma unroll
                for (int ni = grp * 4; ni < grp * 4 + 4; ++ni)
                    #pragma unroll
                    for (int j = 0; j < 2; ++j) {
                        int nloc = wn + ni * 8 + gc2 + j;
                        float d = __fadd_rn(__fadd_rn(xn, sEn[nloc]),
                                            __fmul_rn(-2.0f, acc[mi][ni][half * 2 + j]));
                        unsigned long long key =
                            ((unsigned long long)f2ord(d) << 32) | (unsigned)(n0 + nloc);
                        if (key < k1) { k2 = k1; k1 = key; }
                        else if (key < k2) { k2 = key; }
                    }
                // merge top-2 across the 4 lanes holding this row
                #pragma unroll
                for (int x = 1; x <= 2; x <<= 1) {
                    unsigned long long o1 = __shfl_xor_sync(0xffffffffu, k1, x);
                    unsigned long long o2 = __shfl_xor_sync(0xffffffffu, k2, x);
                    unsigned long long n1 = (k1 < o1) ? k1 : o1;
                    unsigned long long mx = (k1 < o1) ? o1 : k1;
                    unsigned long long mn2 = (k2 < o2) ? k2 : o2;
                    k1 = n1;
                    k2 = (mx < mn2) ? mx : mn2;
                }
                if (gc == 0) {
                    size_t base = ((size_t)(m0 + rl) * NGROUPS + group0 + grp) * 2;
                    g_top2[base]     = k1;
                    g_top2[base + 1] = k2;
                }
            }
        }
    }
}

// ---------------- candidate selection + exact rescore + fused histogram (round-14) ----------------
__global__ void __launch_bounds__(NTHREADS)
vq_candidates(const float* __restrict__ X, const float* __restrict__ W) {
    __shared__ unsigned long long skey[NTHREADS];
    __shared__ int scand[MAXCAND];
    __shared__ int scnt;
    __shared__ unsigned long long sthr;
    __shared__ unsigned long long sbest;

    int b = blockIdx.x;
    int t = threadIdx.x;
    int lane = t & 31;
    int wid  = t >> 5;
    const unsigned long long* keys = g_top2 + (size_t)b * NGROUPS * 2;

    // per-thread min over 4 keys, then tree-min
    unsigned long long mk = ~0ull;
    unsigned long long my[4];
    #pragma unroll
    for (int i = 0; i < 4; ++i) {
        my[i] = keys[t + i * NTHREADS];
        if (my[i] < mk) mk = my[i];
    }
    skey[t] = mk;
    __syncthreads();
    #pragma unroll
    for (int s = NTHREADS / 2; s > 0; s >>= 1) {
        if (t < s && skey[t + s] < skey[t]) skey[t] = skey[t + s];
        __syncthreads();
    }
    if (t == 0) {
        scnt = 0;
        sbest = ~0ull;
        unsigned int mord = (unsigned int)(skey[0] >> 32);
        sthr = ((unsigned long long)(mord + MARGIN_ULPS) << 32) | 0xffffffffull;
    }
    __syncthreads();

    unsigned long long thr = sthr;
    #pragma unroll
    for (int i = 0; i < 4; ++i) {
        if (my[i] <= thr) {
            int pos = atomicAdd(&scnt, 1);
            scand[pos] = (int)(my[i] & 0xffffffffu);   // MAXCAND = key count: no drop possible
        }
    }
    __syncthreads();
    int n = scnt;

    // exact rescore: one candidate per warp, double warp-shuffle reduction
    const float* xr = X + (size_t)b * DIM_;
    float xn = g_xnorm[b];
    for (int i = wid; i < n; i += NTHREADS / 32) {
        int col = scand[i];
        const float* wr = W + (size_t)col * DIM_;
        double s = 0.0;
        for (int k = lane; k < DIM_; k += 32)
            s += (double)xr[k] * (double)wr[k];
        #pragma unroll
        for (int off = 16; off > 0; off >>= 1)
            s += __shfl_down_sync(0xffffffffu, s, off);
        if (lane == 0) {
            float d = __fadd_rn(__fadd_rn(xn, g_enorm[col]), -2.0f * (float)s);
            unsigned long long key = ((unsigned long long)f2ord(d) << 32) | (unsigned)col;
            atomicMin(&sbest, key);
        }
    }
    __syncthreads();
    if (t == 0) {
        g_best[b] = sbest;
        atomicAdd(&g_counts[(int)(sbest & 0xffffffffu)], 1);   // fused histogram
    }
}

// ---------------- quantized output (STE) + loss partials + fused one-hot row ----------------
__global__ void vq_quant(const float* __restrict__ X, const float* __restrict__ W,
                         float* __restrict__ qout, float* __restrict__ enc) {
    int b = blockIdx.x;
    int t = threadIdx.x;
    int idx = (int)(g_best[b] & 0xffffffffu);
    const float4* xr = (const float4*)(X + (size_t)b * DIM_);
    const float4* qr = (const float4*)(W + (size_t)idx * DIM_);
    float* o = qout + (size_t)b * DIM_;   // 4B-aligned only: scalar stores
    double s = 0.0;
    for (int c = t; c < DIM_ / 4; c += NTHREADS) {
        float4 x = xr[c];
        float4 q = qr[c];
        float d0 = __fadd_rn(q.x, -x.x);
        float d1 = __fadd_rn(q.y, -x.y);
        float d2 = __fadd_rn(q.z, -x.z);
        float d3 = __fadd_rn(q.w, -x.w);
        o[4 * c + 0] = __fadd_rn(x.x, d0);
        o[4 * c + 1] = __fadd_rn(x.y, d1);
        o[4 * c + 2] = __fadd_rn(x.z, d2);
        o[4 * c + 3] = __fadd_rn(x.w, d3);
        s += (double)d0 * d0 + (double)d1 * d1 + (double)d2 * d2 + (double)d3 * d3;
    }

    // fused one-hot row (float2 stores: enc base is 8B-aligned)
    float2* er = (float2*)(enc) + (size_t)b * (E_ / 2);
    for (int c2 = t; c2 < E_ / 2; c2 += NTHREADS) {
        int c = c2 * 2;
        float2 v;
        v.x = (c == idx) ? 1.0f : 0.0f;
        v.y = (c + 1 == idx) ? 1.0f : 0.0f;
        er[c2] = v;
    }

    double tot = block_reduce256(s);
    if (t == 0) g_loss_partial[b] = tot;
}

// ---------------- finalize ----------------
__global__ void vq_finalize(float* __restrict__ out_loss, float* __restrict__ out_perp) {
    int t = threadIdx.x;
    double s = 0.0;
    for (int i = t; i < B_; i += NTHREADS) s += g_loss_partial[i];
    double tot = block_reduce256(s);

    double h = 0.0;
    for (int e = t; e < E_; e += NTHREADS) {
        float p = (float)g_counts[e] * (1.0f / (float)B_);
        float term = p * logf(p + 1e-10f);
        h -= (double)term;
    }
    double H = block_reduce256(h);

    if (t == 0) {
        double m = tot / ((double)B_ * (double)DIM_);
        float mf = (float)m;
        out_loss[0] = __fadd_rn(mf, 0.25f * mf);
        out_perp[0] = expf((float)H);
    }
}

// ---------------- launch ----------------
extern "C" void kernel_launch(void* const* d_in, const int* in_sizes, int n_in,
                              void* d_out, int out_size) {
    const float* X;
    const float* W;
    if (in_sizes[0] == B_ * DIM_) {
        X = (const float*)d_in[0];
        W = (const float*)d_in[1];
    } else {
        X = (const float*)d_in[1];
        W = (const float*)d_in[0];
    }

    float* out = (float*)d_out;
    float* out_loss = out;
    float* out_q    = out + 1;
    float* out_perp = out + 1 + (size_t)B_ * DIM_;
    float* out_enc  = out + 2 + (size_t)B_ * DIM_;

    float* xnorm;  cudaGetSymbolAddress((void**)&xnorm, g_xnorm);
    float* enorm;  cudaGetSymbolAddress((void**)&enorm, g_enorm);
    unsigned short *xb, *wb;
    cudaGetSymbolAddress((void**)&xb, g_Xb);
    cudaGetSymbolAddress((void**)&wb, g_Wb);

    vq_init<<<E_ / NTHREADS, NTHREADS>>>();
    vq_prep<<<B_, NTHREADS>>>(X, xb, xnorm);
    vq_prep<<<E_, NTHREADS>>>(W, wb, enorm);

    cudaFuncSetAttribute(vq_gemm_mma, cudaFuncAttributeMaxDynamicSharedMemorySize, SMEM_TOTAL);
    dim3 grid(B_ / TILE_M, E_ / TILE_N);   // x = M fastest: B tiles reused in L2
    vq_gemm_mma<<<grid, NTHREADS, SMEM_TOTAL>>>(xb, wb);

    vq_candidates<<<B_, NTHREADS>>>(X, W);

    vq_quant<<<B_, NTHREADS>>>(X, W, out_q, out_enc);

    vq_finalize<<<1, NTHREADS>>>(out_loss, out_perp);
}